// round 1
// baseline (speedup 1.0000x reference)
#include <cuda_runtime.h>
#include <cstdint>

// ---------------- problem constants ----------------
#define B_TOK 65536
#define I_DIM 512
#define H_DIM 128
#define T_NUM 2
#define ETOT  6
#define NE    8                 // packed experts: t0e0,t0e1,t1e0,t1e1,c0..c3
#define N_DIM (NE * H_DIM)      // 1024
#define K_DIM I_DIM             // 512

// ---------------- scratch (device globals; no allocs allowed) ----------------
__device__ float g_Wpack[K_DIM * N_DIM];          // [k][n], n = e*128 + h  (2 MB)
__device__ float g_bpack[N_DIM];
__device__ float g_tmp[(size_t)B_TOK * N_DIM];    // expert outputs [b][n]  (256 MB)

// ---------------- helpers ----------------
__device__ __forceinline__ uint32_t smem_u32(const void* p) {
    uint32_t a;
    asm("{ .reg .u64 t; cvta.to.shared.u64 t, %1; cvt.u32.u64 %0, t; }"
        : "=r"(a) : "l"(p));
    return a;
}

__device__ __forceinline__ uint32_t f2tf(float x) {
    uint32_t r;
    asm("cvt.rna.tf32.f32 %0, %1;" : "=r"(r) : "f"(x));
    return r;
}

__device__ __forceinline__ void mma8(float* c, const uint32_t* a, const uint32_t* b) {
    asm volatile(
        "mma.sync.aligned.m16n8k8.row.col.f32.tf32.tf32.f32 "
        "{%0,%1,%2,%3}, {%4,%5,%6,%7}, {%8,%9}, {%0,%1,%2,%3};"
        : "+f"(c[0]), "+f"(c[1]), "+f"(c[2]), "+f"(c[3])
        : "r"(a[0]), "r"(a[1]), "r"(a[2]), "r"(a[3]), "r"(b[0]), "r"(b[1]));
}

#define CP_ASYNC16(dst, src) \
    asm volatile("cp.async.cg.shared.global [%0], [%1], 16;\n" :: "r"(dst), "l"(src))
#define CP_COMMIT() asm volatile("cp.async.commit_group;\n")
#define CP_WAIT1()  asm volatile("cp.async.wait_group 1;\n")
#define CP_WAIT0()  asm volatile("cp.async.wait_group 0;\n")

// ---------------- kernel 1: pack weights / biases ----------------
__global__ void prep_kernel(const float* __restrict__ Wc, const float* __restrict__ bc,
                            const float* __restrict__ Ws, const float* __restrict__ bs) {
    int idx = blockIdx.x * blockDim.x + threadIdx.x;
    if (idx < K_DIM * N_DIM) {
        int k = idx / N_DIM, n = idx % N_DIM;
        int e = n / H_DIM,   h = n % H_DIM;
        // e<4: Ws[t][es] with e = t*2+es ; e>=4: Wc[e-4]
        float v = (e < 4) ? Ws[((size_t)e * I_DIM + k) * H_DIM + h]
                          : Wc[((size_t)(e - 4) * I_DIM + k) * H_DIM + h];
        g_Wpack[idx] = v;
    }
    if (idx < N_DIM) {
        int e = idx / H_DIM, h = idx % H_DIM;
        g_bpack[idx] = (e < 4) ? bs[e * H_DIM + h] : bc[(e - 4) * H_DIM + h];
    }
}

// ---------------- kernel 2: fused expert GEMM (tf32, split-x) ----------------
// C[B,1024] = x[B,512] @ Wpack[512,1024] + bpack, accuracy via x = x_hi + x_lo.
#define BM 128
#define BN 128
#define BK 32
#define A_PITCH 36    // 128x(32) + pad 4 -> conflict-free frag loads
#define B_PITCH 136   // 32x(128) + pad 8 -> conflict-free frag loads
#define A_SZ (BM * A_PITCH)   // 4608 floats
#define B_SZ (BK * B_PITCH)   // 4352 floats
#define SMEM_BYTES (2 * (A_SZ + B_SZ) * 4)  // 71680

__global__ __launch_bounds__(256) void gemm_kernel(const float* __restrict__ x) {
    extern __shared__ float smem[];
    float* As[2] = { smem, smem + A_SZ };
    float* Bs[2] = { smem + 2 * A_SZ, smem + 2 * A_SZ + B_SZ };
    const uint32_t sA[2] = { smem_u32(As[0]), smem_u32(As[1]) };
    const uint32_t sB[2] = { smem_u32(Bs[0]), smem_u32(Bs[1]) };

    const int tid  = threadIdx.x;
    const int wid  = tid >> 5, lane = tid & 31;
    const int g    = lane >> 2, tg = lane & 3;      // groupID, threadID_in_group
    const int wm   = wid >> 2, wn = wid & 3;        // 2x4 warp grid -> 64x32 per warp
    const int m0   = blockIdx.y * BM, n0 = blockIdx.x * BN;

    float acc[4][4][4];
    #pragma unroll
    for (int i = 0; i < 4; i++)
        #pragma unroll
        for (int j = 0; j < 4; j++)
            #pragma unroll
            for (int c = 0; c < 4; c++) acc[i][j][c] = 0.f;

    auto load_stage = [&](int kt, int buf) {
        const int kb = kt * BK;
        #pragma unroll
        for (int i = 0; i < 4; i++) {          // A tile: 128 rows x 8 float4
            int f   = tid + i * 256;
            int row = f >> 3, kc = f & 7;
            const float* src = x + (size_t)(m0 + row) * K_DIM + kb + kc * 4;
            CP_ASYNC16(sA[buf] + (uint32_t)(row * A_PITCH + kc * 4) * 4, src);
        }
        #pragma unroll
        for (int i = 0; i < 4; i++) {          // B tile: 32 rows x 32 float4
            int f = tid + i * 256;
            int k = f >> 5, nc = f & 31;
            const float* src = g_Wpack + (size_t)(kb + k) * N_DIM + n0 + nc * 4;
            CP_ASYNC16(sB[buf] + (uint32_t)(k * B_PITCH + nc * 4) * 4, src);
        }
    };

    auto compute = [&](int buf) {
        const float* A  = As[buf];
        const float* Bt = Bs[buf];
        #pragma unroll
        for (int ks = 0; ks < 4; ks++) {
            const int kb = ks * 8;
            uint32_t ah[4][4], al[4][4];
            #pragma unroll
            for (int mt = 0; mt < 4; mt++) {
                int r0 = wm * 64 + mt * 16 + g;
                float v0 = A[(r0    ) * A_PITCH + kb + tg    ];
                float v1 = A[(r0 + 8) * A_PITCH + kb + tg    ];
                float v2 = A[(r0    ) * A_PITCH + kb + tg + 4];
                float v3 = A[(r0 + 8) * A_PITCH + kb + tg + 4];
                ah[mt][0] = f2tf(v0); al[mt][0] = f2tf(v0 - __uint_as_float(ah[mt][0]));
                ah[mt][1] = f2tf(v1); al[mt][1] = f2tf(v1 - __uint_as_float(ah[mt][1]));
                ah[mt][2] = f2tf(v2); al[mt][2] = f2tf(v2 - __uint_as_float(ah[mt][2]));
                ah[mt][3] = f2tf(v3); al[mt][3] = f2tf(v3 - __uint_as_float(ah[mt][3]));
            }
            uint32_t bb[4][2];
            #pragma unroll
            for (int nt = 0; nt < 4; nt++) {
                int c0 = wn * 32 + nt * 8 + g;
                bb[nt][0] = f2tf(Bt[(kb + tg    ) * B_PITCH + c0]);
                bb[nt][1] = f2tf(Bt[(kb + tg + 4) * B_PITCH + c0]);
            }
            #pragma unroll
            for (int mt = 0; mt < 4; mt++)
                #pragma unroll
                for (int nt = 0; nt < 4; nt++) {
                    mma8(acc[mt][nt], ah[mt], bb[nt]);
                    mma8(acc[mt][nt], al[mt], bb[nt]);
                }
        }
    };

    load_stage(0, 0);
    CP_COMMIT();
    #pragma unroll 1
    for (int kt = 0; kt < K_DIM / BK; kt++) {
        if (kt + 1 < K_DIM / BK) {
            load_stage(kt + 1, (kt + 1) & 1);
            CP_COMMIT();
            CP_WAIT1();
        } else {
            CP_WAIT0();
        }
        __syncthreads();
        compute(kt & 1);
        __syncthreads();
    }

    // epilogue: add bias, store fp32 to g_tmp
    #pragma unroll
    for (int mt = 0; mt < 4; mt++)
        #pragma unroll
        for (int nt = 0; nt < 4; nt++) {
            int row = m0 + wm * 64 + mt * 16 + g;
            int col = n0 + wn * 32 + nt * 8 + 2 * tg;
            float b0 = g_bpack[col], b1 = g_bpack[col + 1];
            float2 v0 = make_float2(acc[mt][nt][0] + b0, acc[mt][nt][1] + b1);
            float2 v1 = make_float2(acc[mt][nt][2] + b0, acc[mt][nt][3] + b1);
            *reinterpret_cast<float2*>(&g_tmp[(size_t)(row    ) * N_DIM + col]) = v0;
            *reinterpret_cast<float2*>(&g_tmp[(size_t)(row + 8) * N_DIM + col]) = v1;
        }
}

// ---------------- kernel 3: gate + weighted feature + final projection ----------------
// warp-per-token, both tasks per warp (g_tmp row read once).
__global__ __launch_bounds__(256) void gate_kernel(const float* __restrict__ Wg,
                                                   const float* __restrict__ bg,
                                                   const float* __restrict__ Wt,
                                                   const float* __restrict__ bt,
                                                   float* __restrict__ out) {
    __shared__ float sWg[T_NUM][ETOT][ETOT * H_DIM];   // transposed: [t][j][f]
    __shared__ float sWt[T_NUM][H_DIM];
    __shared__ float sbg[T_NUM][ETOT];
    __shared__ float sbt[T_NUM];

    const int tid = threadIdx.x;
    for (int idx = tid; idx < T_NUM * ETOT * H_DIM * ETOT; idx += 256) {
        int t = idx / (ETOT * H_DIM * ETOT);
        int rem = idx % (ETOT * H_DIM * ETOT);
        int f = rem / ETOT, j = rem % ETOT;
        sWg[t][j][f] = Wg[idx];                        // Wg is [t][f][j]
    }
    for (int idx = tid; idx < T_NUM * H_DIM; idx += 256)
        sWt[idx / H_DIM][idx % H_DIM] = Wt[idx];
    if (tid < T_NUM * ETOT) sbg[tid / ETOT][tid % ETOT] = bg[tid];
    if (tid < T_NUM) sbt[tid] = bt[tid];
    __syncthreads();

    const int w = tid >> 5, l = tid & 31;
    const int b = blockIdx.x * 8 + w;

    // lane l holds h = 4l..4l+3 of every packed expert e
    float4 r[NE];
    const float4* rowp = reinterpret_cast<const float4*>(g_tmp + (size_t)b * N_DIM);
    #pragma unroll
    for (int e = 0; e < NE; e++) r[e] = rowp[e * 32 + l];

    #pragma unroll
    for (int t = 0; t < T_NUM; t++) {
        float lg[ETOT] = {0.f, 0.f, 0.f, 0.f, 0.f, 0.f};
        #pragma unroll
        for (int eo = 0; eo < ETOT; eo++) {
            int e = (eo < 2) ? (2 * t + eo) : (eo + 2);
            float4 gi = r[e];
            const float4* wr;
            #pragma unroll
            for (int j = 0; j < ETOT; j++) {
                wr = reinterpret_cast<const float4*>(sWg[t][j]);
                float4 wv = wr[eo * 32 + l];
                lg[j] += gi.x * wv.x + gi.y * wv.y + gi.z * wv.z + gi.w * wv.w;
            }
        }
        #pragma unroll
        for (int j = 0; j < ETOT; j++) {
            #pragma unroll
            for (int off = 16; off > 0; off >>= 1)
                lg[j] += __shfl_xor_sync(0xffffffffu, lg[j], off);
            lg[j] += sbg[t][j];
        }
        float m = lg[0];
        #pragma unroll
        for (int j = 1; j < ETOT; j++) m = fmaxf(m, lg[j]);
        float ex[ETOT], s = 0.f;
        #pragma unroll
        for (int j = 0; j < ETOT; j++) { ex[j] = expf(lg[j] - m); s += ex[j]; }
        float inv = 1.f / s;

        float4 feat = make_float4(0.f, 0.f, 0.f, 0.f);
        #pragma unroll
        for (int eo = 0; eo < ETOT; eo++) {
            int e = (eo < 2) ? (2 * t + eo) : (eo + 2);
            float wgt = ex[eo] * inv;
            feat.x += wgt * r[e].x; feat.y += wgt * r[e].y;
            feat.z += wgt * r[e].z; feat.w += wgt * r[e].w;
        }
        float p = feat.x * sWt[t][4 * l] + feat.y * sWt[t][4 * l + 1] +
                  feat.z * sWt[t][4 * l + 2] + feat.w * sWt[t][4 * l + 3];
        #pragma unroll
        for (int off = 16; off > 0; off >>= 1)
            p += __shfl_xor_sync(0xffffffffu, p, off);
        if (l == 0) out[t * B_TOK + b] = p + sbt[t];
    }
}

// ---------------- launch ----------------
extern "C" void kernel_launch(void* const* d_in, const int* in_sizes, int n_in,
                              void* d_out, int out_size) {
    const float* x  = (const float*)d_in[0];
    const float* Wc = (const float*)d_in[1];
    const float* bc = (const float*)d_in[2];
    const float* Ws = (const float*)d_in[3];
    const float* bs = (const float*)d_in[4];
    const float* Wg = (const float*)d_in[5];
    const float* bg = (const float*)d_in[6];
    const float* Wt = (const float*)d_in[7];
    const float* bt = (const float*)d_in[8];
    float* out = (float*)d_out;

    prep_kernel<<<(K_DIM * N_DIM + 255) / 256, 256>>>(Wc, bc, Ws, bs);

    cudaFuncSetAttribute(gemm_kernel, cudaFuncAttributeMaxDynamicSharedMemorySize,
                         SMEM_BYTES);
    gemm_kernel<<<dim3(N_DIM / BN, B_TOK / BM), 256, SMEM_BYTES>>>(x);

    gate_kernel<<<B_TOK / 8, 256>>>(Wg, bg, Wt, bt, out);
}

// round 5
// speedup vs baseline: 1.7147x; 1.7147x over previous
#include <cuda_runtime.h>
#include <cstdint>

// ---------------- problem constants ----------------
#define B_TOK 65536
#define I_DIM 512
#define H_DIM 128
#define T_NUM 2
#define ETOT  6
#define NE    8                 // packed experts: t0e0,t0e1,t1e0,t1e1,c0..c3
#define N_DIM (NE * H_DIM)      // 1024
#define K_DIM I_DIM             // 512

// ---------------- scratch (device globals; no allocs allowed) ----------------
__device__ __align__(256) float g_Wpack[K_DIM * N_DIM];          // [k][n], tf32-rounded (2 MB)
__device__ __align__(256) float g_bpack[N_DIM];
__device__ __align__(256) float g_xr[(size_t)B_TOK * K_DIM];     // tf32-rounded x (128 MB)
__device__ __align__(256) float g_tmp[(size_t)B_TOK * N_DIM];    // expert outputs (256 MB)

// ---------------- helpers ----------------
__device__ __forceinline__ uint32_t f2tf(float x) {
    uint32_t r;
    asm("cvt.rna.tf32.f32 %0, %1;" : "=r"(r) : "f"(x));
    return r;
}

__device__ __forceinline__ void mma8(float* c, const uint32_t* a, const uint32_t* b) {
    asm volatile(
        "mma.sync.aligned.m16n8k8.row.col.f32.tf32.tf32.f32 "
        "{%0,%1,%2,%3}, {%4,%5,%6,%7}, {%8,%9}, {%0,%1,%2,%3};"
        : "+f"(c[0]), "+f"(c[1]), "+f"(c[2]), "+f"(c[3])
        : "r"(a[0]), "r"(a[1]), "r"(a[2]), "r"(a[3]), "r"(b[0]), "r"(b[1]));
}

#define CP_ASYNC16(dst, src) \
    asm volatile("cp.async.cg.shared.global [%0], [%1], 16;\n" :: "r"(dst), "l"(src))
#define CP_COMMIT() asm volatile("cp.async.commit_group;\n")
#define CP_WAIT1()  asm volatile("cp.async.wait_group 1;\n")
#define CP_WAIT0()  asm volatile("cp.async.wait_group 0;\n")

__device__ __forceinline__ uint32_t smem_u32(const void* p) {
    uint32_t a;
    asm("{ .reg .u64 t; cvta.to.shared.u64 t, %1; cvt.u32.u64 %0, t; }"
        : "=r"(a) : "l"(p));
    return a;
}

// ---------------- kernel 1a: pack + tf32-round weights, pack bias ----------------
__global__ void prep_w_kernel(const float* __restrict__ Wc, const float* __restrict__ bc,
                              const float* __restrict__ Ws, const float* __restrict__ bs) {
    int idx = blockIdx.x * blockDim.x + threadIdx.x;
    if (idx < K_DIM * N_DIM) {
        int k = idx / N_DIM, n = idx % N_DIM;
        int e = n / H_DIM,   h = n % H_DIM;
        // e<4: Ws[t][es] with e = t*2+es ; e>=4: Wc[e-4]
        float v = (e < 4) ? Ws[((size_t)e * I_DIM + k) * H_DIM + h]
                          : Wc[((size_t)(e - 4) * I_DIM + k) * H_DIM + h];
        g_Wpack[idx] = __uint_as_float(f2tf(v));
    }
    if (idx < N_DIM) {
        int e = idx / H_DIM, h = idx % H_DIM;
        g_bpack[idx] = (e < 4) ? bs[e * H_DIM + h] : bc[(e - 4) * H_DIM + h];
    }
}

// ---------------- kernel 1b: tf32-round x (RN) so in-MMA truncation is exact ----
__global__ void prep_x_kernel(const float* __restrict__ x) {
    size_t n4 = (size_t)B_TOK * K_DIM / 4;
    const float4* src = reinterpret_cast<const float4*>(x);
    float4* dst = reinterpret_cast<float4*>(g_xr);
    for (size_t i = blockIdx.x * blockDim.x + threadIdx.x; i < n4;
         i += (size_t)gridDim.x * blockDim.x) {
        float4 v = src[i];
        v.x = __uint_as_float(f2tf(v.x));
        v.y = __uint_as_float(f2tf(v.y));
        v.z = __uint_as_float(f2tf(v.z));
        v.w = __uint_as_float(f2tf(v.w));
        dst[i] = v;
    }
}

// ---------------- kernel 2: fused expert GEMM (single tf32 chain) ----------------
// g_tmp[B,1024] = g_xr[B,512] @ g_Wpack[512,1024] + g_bpack
#define BM 128
#define BN 128
#define BK 32
#define A_PITCH 36    // 128x32 + pad 4 -> bank = (4g+tg+kb)%32, conflict-free
#define B_PITCH 136   // 32x128 + pad 8 -> bank = (8tg+g)%32,   conflict-free
#define A_SZ (BM * A_PITCH)   // 4608 floats
#define B_SZ (BK * B_PITCH)   // 4352 floats
#define SMEM_BYTES (2 * (A_SZ + B_SZ) * 4)  // 71680

__global__ __launch_bounds__(256) void gemm_kernel() {
    extern __shared__ float smem[];
    float* As[2] = { smem, smem + A_SZ };
    float* Bs[2] = { smem + 2 * A_SZ, smem + 2 * A_SZ + B_SZ };
    const uint32_t sA[2] = { smem_u32(As[0]), smem_u32(As[1]) };
    const uint32_t sB[2] = { smem_u32(Bs[0]), smem_u32(Bs[1]) };

    const int tid  = threadIdx.x;
    const int wid  = tid >> 5, lane = tid & 31;
    const int g    = lane >> 2, tg = lane & 3;      // groupID, threadID_in_group
    const int wm   = wid >> 2, wn = wid & 3;        // 2x4 warp grid -> 64x32 per warp
    const int m0   = blockIdx.y * BM, n0 = blockIdx.x * BN;

    float acc[4][4][4];
    #pragma unroll
    for (int i = 0; i < 4; i++)
        #pragma unroll
        for (int j = 0; j < 4; j++)
            #pragma unroll
            for (int c = 0; c < 4; c++) acc[i][j][c] = 0.f;

    auto load_stage = [&](int kt, int buf) {
        const int kb = kt * BK;
        #pragma unroll
        for (int i = 0; i < 4; i++) {          // A tile: 128 rows x 8 float4
            int f   = tid + i * 256;
            int row = f >> 3, kc = f & 7;
            const float* src = g_xr + (size_t)(m0 + row) * K_DIM + kb + kc * 4;
            CP_ASYNC16(sA[buf] + (uint32_t)(row * A_PITCH + kc * 4) * 4, src);
        }
        #pragma unroll
        for (int i = 0; i < 4; i++) {          // B tile: 32 rows x 32 float4
            int f = tid + i * 256;
            int k = f >> 5, nc = f & 31;
            const float* src = g_Wpack + (size_t)(kb + k) * N_DIM + n0 + nc * 4;
            CP_ASYNC16(sB[buf] + (uint32_t)(k * B_PITCH + nc * 4) * 4, src);
        }
    };

    auto compute = [&](int buf) {
        const uint32_t* A  = reinterpret_cast<const uint32_t*>(As[buf]);
        const uint32_t* Bt = reinterpret_cast<const uint32_t*>(Bs[buf]);
        #pragma unroll
        for (int ks = 0; ks < 4; ks++) {
            const int kb = ks * 8;
            uint32_t af[4][4];
            #pragma unroll
            for (int mt = 0; mt < 4; mt++) {
                int r0 = wm * 64 + mt * 16 + g;
                af[mt][0] = A[(r0    ) * A_PITCH + kb + tg    ];
                af[mt][1] = A[(r0 + 8) * A_PITCH + kb + tg    ];
                af[mt][2] = A[(r0    ) * A_PITCH + kb + tg + 4];
                af[mt][3] = A[(r0 + 8) * A_PITCH + kb + tg + 4];
            }
            uint32_t bb[4][2];
            #pragma unroll
            for (int nt = 0; nt < 4; nt++) {
                int c0 = wn * 32 + nt * 8 + g;
                bb[nt][0] = Bt[(kb + tg    ) * B_PITCH + c0];
                bb[nt][1] = Bt[(kb + tg + 4) * B_PITCH + c0];
            }
            #pragma unroll
            for (int mt = 0; mt < 4; mt++)
                #pragma unroll
                for (int nt = 0; nt < 4; nt++)
                    mma8(acc[mt][nt], af[mt], bb[nt]);
        }
    };

    load_stage(0, 0);
    CP_COMMIT();
    #pragma unroll 1
    for (int kt = 0; kt < K_DIM / BK; kt++) {
        if (kt + 1 < K_DIM / BK) {
            load_stage(kt + 1, (kt + 1) & 1);
            CP_COMMIT();
            CP_WAIT1();
        } else {
            CP_WAIT0();
        }
        __syncthreads();
        compute(kt & 1);
        __syncthreads();
    }

    // epilogue: add bias, store fp32 to g_tmp
    #pragma unroll
    for (int mt = 0; mt < 4; mt++)
        #pragma unroll
        for (int nt = 0; nt < 4; nt++) {
            int row = m0 + wm * 64 + mt * 16 + g;
            int col = n0 + wn * 32 + nt * 8 + 2 * tg;
            float b0 = g_bpack[col], b1 = g_bpack[col + 1];
            float2 v0 = make_float2(acc[mt][nt][0] + b0, acc[mt][nt][1] + b1);
            float2 v1 = make_float2(acc[mt][nt][2] + b0, acc[mt][nt][3] + b1);
            *reinterpret_cast<float2*>(&g_tmp[(size_t)(row    ) * N_DIM + col]) = v0;
            *reinterpret_cast<float2*>(&g_tmp[(size_t)(row + 8) * N_DIM + col]) = v1;
        }
}

// ---------------- kernel 3: gate + weighted feature + final projection ----------------
// warp-per-token, both tasks per warp (g_tmp row read once).
__global__ __launch_bounds__(256) void gate_kernel(const float* __restrict__ Wg,
                                                   const float* __restrict__ bg,
                                                   const float* __restrict__ Wt,
                                                   const float* __restrict__ bt,
                                                   float* __restrict__ out) {
    __shared__ float sWg[T_NUM][ETOT][ETOT * H_DIM];   // transposed: [t][j][f]
    __shared__ float sWt[T_NUM][H_DIM];
    __shared__ float sbg[T_NUM][ETOT];
    __shared__ float sbt[T_NUM];

    const int tid = threadIdx.x;
    for (int idx = tid; idx < T_NUM * ETOT * H_DIM * ETOT; idx += 256) {
        int t = idx / (ETOT * H_DIM * ETOT);
        int rem = idx % (ETOT * H_DIM * ETOT);
        int f = rem / ETOT, j = rem % ETOT;
        sWg[t][j][f] = Wg[idx];                        // Wg is [t][f][j]
    }
    for (int idx = tid; idx < T_NUM * H_DIM; idx += 256)
        sWt[idx / H_DIM][idx % H_DIM] = Wt[idx];
    if (tid < T_NUM * ETOT) sbg[tid / ETOT][tid % ETOT] = bg[tid];
    if (tid < T_NUM) sbt[tid] = bt[tid];
    __syncthreads();

    const int w = tid >> 5, l = tid & 31;
    const int b = blockIdx.x * 8 + w;

    // lane l holds h = 4l..4l+3 of every packed expert e
    float4 r[NE];
    const float4* rowp = reinterpret_cast<const float4*>(g_tmp + (size_t)b * N_DIM);
    #pragma unroll
    for (int e = 0; e < NE; e++) r[e] = rowp[e * 32 + l];

    #pragma unroll
    for (int t = 0; t < T_NUM; t++) {
        float lg[ETOT] = {0.f, 0.f, 0.f, 0.f, 0.f, 0.f};
        #pragma unroll
        for (int eo = 0; eo < ETOT; eo++) {
            int e = (eo < 2) ? (2 * t + eo) : (eo + 2);
            float4 gi = r[e];
            #pragma unroll
            for (int j = 0; j < ETOT; j++) {
                const float4* wr = reinterpret_cast<const float4*>(sWg[t][j]);
                float4 wv = wr[eo * 32 + l];
                lg[j] += gi.x * wv.x + gi.y * wv.y + gi.z * wv.z + gi.w * wv.w;
            }
        }
        #pragma unroll
        for (int j = 0; j < ETOT; j++) {
            #pragma unroll
            for (int off = 16; off > 0; off >>= 1)
                lg[j] += __shfl_xor_sync(0xffffffffu, lg[j], off);
            lg[j] += sbg[t][j];
        }
        float m = lg[0];
        #pragma unroll
        for (int j = 1; j < ETOT; j++) m = fmaxf(m, lg[j]);
        float ex[ETOT], ssum = 0.f;
        #pragma unroll
        for (int j = 0; j < ETOT; j++) { ex[j] = expf(lg[j] - m); ssum += ex[j]; }
        float inv = 1.f / ssum;

        float4 feat = make_float4(0.f, 0.f, 0.f, 0.f);
        #pragma unroll
        for (int eo = 0; eo < ETOT; eo++) {
            int e = (eo < 2) ? (2 * t + eo) : (eo + 2);
            float wgt = ex[eo] * inv;
            feat.x += wgt * r[e].x; feat.y += wgt * r[e].y;
            feat.z += wgt * r[e].z; feat.w += wgt * r[e].w;
        }
        float p = feat.x * sWt[t][4 * l] + feat.y * sWt[t][4 * l + 1] +
                  feat.z * sWt[t][4 * l + 2] + feat.w * sWt[t][4 * l + 3];
        #pragma unroll
        for (int off = 16; off > 0; off >>= 1)
            p += __shfl_xor_sync(0xffffffffu, p, off);
        if (l == 0) out[t * B_TOK + b] = p + sbt[t];
    }
}

// ---------------- launch ----------------
extern "C" void kernel_launch(void* const* d_in, const int* in_sizes, int n_in,
                              void* d_out, int out_size) {
    const float* x  = (const float*)d_in[0];
    const float* Wc = (const float*)d_in[1];
    const float* bc = (const float*)d_in[2];
    const float* Ws = (const float*)d_in[3];
    const float* bs = (const float*)d_in[4];
    const float* Wg = (const float*)d_in[5];
    const float* bg = (const float*)d_in[6];
    const float* Wt = (const float*)d_in[7];
    const float* bt = (const float*)d_in[8];
    float* out = (float*)d_out;

    prep_w_kernel<<<(K_DIM * N_DIM + 255) / 256, 256>>>(Wc, bc, Ws, bs);
    prep_x_kernel<<<8192, 256>>>(x);

    cudaFuncSetAttribute(gemm_kernel, cudaFuncAttributeMaxDynamicSharedMemorySize,
                         SMEM_BYTES);
    gemm_kernel<<<dim3(N_DIM / BN, B_TOK / BM), 256, SMEM_BYTES>>>();

    gate_kernel<<<B_TOK / 8, 256>>>(Wg, bg, Wt, bt, out);
}

// round 6
// speedup vs baseline: 2.0354x; 1.1871x over previous
#include <cuda_runtime.h>
#include <cuda_fp16.h>
#include <cstdint>

// ---------------- problem constants ----------------
#define B_TOK 65536
#define I_DIM 512
#define H_DIM 128
#define T_NUM 2
#define ETOT  6
#define NE    8                 // packed experts: t0e0,t0e1,t1e0,t1e1,c0..c3
#define N_DIM (NE * H_DIM)      // 1024
#define K_DIM I_DIM             // 512

// ---------------- scratch (device globals; no allocs allowed) ----------------
__device__ __align__(256) float g_Wpack[K_DIM * N_DIM];          // [k][n], tf32-rounded (2 MB)
__device__ __align__(256) float g_bpack[N_DIM];
__device__ __align__(256) float g_tmp[(size_t)B_TOK * N_DIM];    // expert outputs (256 MB)

// ---------------- helpers ----------------
__device__ __forceinline__ uint32_t f2tf(float x) {
    uint32_t r;
    asm("cvt.rna.tf32.f32 %0, %1;" : "=r"(r) : "f"(x));
    return r;
}

__device__ __forceinline__ void mma8(float* c, const uint32_t* a, const uint32_t* b) {
    asm volatile(
        "mma.sync.aligned.m16n8k8.row.col.f32.tf32.tf32.f32 "
        "{%0,%1,%2,%3}, {%4,%5,%6,%7}, {%8,%9}, {%0,%1,%2,%3};"
        : "+f"(c[0]), "+f"(c[1]), "+f"(c[2]), "+f"(c[3])
        : "r"(a[0]), "r"(a[1]), "r"(a[2]), "r"(a[3]), "r"(b[0]), "r"(b[1]));
}

#define CP_ASYNC16(dst, src) \
    asm volatile("cp.async.cg.shared.global [%0], [%1], 16;\n" :: "r"(dst), "l"(src))
#define CP_COMMIT() asm volatile("cp.async.commit_group;\n")
#define CP_WAIT1()  asm volatile("cp.async.wait_group 1;\n")
#define CP_WAIT0()  asm volatile("cp.async.wait_group 0;\n")

__device__ __forceinline__ uint32_t smem_u32(const void* p) {
    uint32_t a;
    asm("{ .reg .u64 t; cvta.to.shared.u64 t, %1; cvt.u32.u64 %0, t; }"
        : "=r"(a) : "l"(p));
    return a;
}

// ---------------- kernel 1: pack + tf32-round weights, pack bias ----------------
__global__ void prep_w_kernel(const float* __restrict__ Wc, const float* __restrict__ bc,
                              const float* __restrict__ Ws, const float* __restrict__ bs) {
    int idx = blockIdx.x * blockDim.x + threadIdx.x;
    if (idx < K_DIM * N_DIM) {
        int k = idx / N_DIM, n = idx % N_DIM;
        int e = n / H_DIM,   h = n % H_DIM;
        float v = (e < 4) ? Ws[((size_t)e * I_DIM + k) * H_DIM + h]
                          : Wc[((size_t)(e - 4) * I_DIM + k) * H_DIM + h];
        g_Wpack[idx] = __uint_as_float(f2tf(v));
    }
    if (idx < N_DIM) {
        int e = idx / H_DIM, h = idx % H_DIM;
        g_bpack[idx] = (e < 4) ? bs[e * H_DIM + h] : bc[(e - 4) * H_DIM + h];
    }
}

// ---------------- kernel 2: fused expert GEMM (tf32, warp tile 64x64) -----------
// g_tmp[B,1024] = x[B,512] @ g_Wpack[512,1024] + g_bpack
// CTA 128x128, 4 warps (2x2), 128 acc regs/thread. A frags cvt'd to tf32 inline.
#define BM 128
#define BN 128
#define BK 32
#define A_PITCH 36    // bank = (4g+tg)%32 -> conflict-free
#define B_PITCH 136   // bank = (8tg+g)%32 -> conflict-free
#define A_SZ (BM * A_PITCH)   // 4608 floats
#define B_SZ (BK * B_PITCH)   // 4352 floats
#define SMEM_BYTES (2 * (A_SZ + B_SZ) * 4)  // 71680

__global__ __launch_bounds__(128) void gemm_kernel(const float* __restrict__ x) {
    extern __shared__ float smem[];
    float* As[2] = { smem, smem + A_SZ };
    float* Bs[2] = { smem + 2 * A_SZ, smem + 2 * A_SZ + B_SZ };
    const uint32_t sA[2] = { smem_u32(As[0]), smem_u32(As[1]) };
    const uint32_t sB[2] = { smem_u32(Bs[0]), smem_u32(Bs[1]) };

    const int tid  = threadIdx.x;
    const int wid  = tid >> 5, lane = tid & 31;
    const int g    = lane >> 2, tg = lane & 3;
    const int wm   = wid >> 1, wn = wid & 1;        // 2x2 warp grid, 64x64 per warp
    const int m0   = blockIdx.y * BM, n0 = blockIdx.x * BN;

    float acc[4][8][4];
    #pragma unroll
    for (int i = 0; i < 4; i++)
        #pragma unroll
        for (int j = 0; j < 8; j++)
            #pragma unroll
            for (int c = 0; c < 4; c++) acc[i][j][c] = 0.f;

    auto load_stage = [&](int kt, int buf) {
        const int kb = kt * BK;
        #pragma unroll
        for (int i = 0; i < 8; i++) {          // A tile: 128 rows x 8 float4
            int f   = tid + i * 128;
            int row = f >> 3, kc = f & 7;
            const float* src = x + (size_t)(m0 + row) * K_DIM + kb + kc * 4;
            CP_ASYNC16(sA[buf] + (uint32_t)(row * A_PITCH + kc * 4) * 4, src);
        }
        #pragma unroll
        for (int i = 0; i < 8; i++) {          // B tile: 32 rows x 32 float4
            int f = tid + i * 128;
            int k = f >> 5, nc = f & 31;
            const float* src = g_Wpack + (size_t)(kb + k) * N_DIM + n0 + nc * 4;
            CP_ASYNC16(sB[buf] + (uint32_t)(k * B_PITCH + nc * 4) * 4, src);
        }
    };

    auto compute = [&](int buf) {
        const float*    A  = As[buf];
        const uint32_t* Bt = reinterpret_cast<const uint32_t*>(Bs[buf]);
        #pragma unroll
        for (int ks = 0; ks < 4; ks++) {
            const int kb = ks * 8;
            uint32_t af[4][4];
            #pragma unroll
            for (int mt = 0; mt < 4; mt++) {
                int r0 = wm * 64 + mt * 16 + g;
                af[mt][0] = f2tf(A[(r0    ) * A_PITCH + kb + tg    ]);
                af[mt][1] = f2tf(A[(r0 + 8) * A_PITCH + kb + tg    ]);
                af[mt][2] = f2tf(A[(r0    ) * A_PITCH + kb + tg + 4]);
                af[mt][3] = f2tf(A[(r0 + 8) * A_PITCH + kb + tg + 4]);
            }
            uint32_t bb[8][2];
            #pragma unroll
            for (int nt = 0; nt < 8; nt++) {
                int c0 = wn * 64 + nt * 8 + g;
                bb[nt][0] = Bt[(kb + tg    ) * B_PITCH + c0];
                bb[nt][1] = Bt[(kb + tg + 4) * B_PITCH + c0];
            }
            #pragma unroll
            for (int mt = 0; mt < 4; mt++)
                #pragma unroll
                for (int nt = 0; nt < 8; nt++)
                    mma8(acc[mt][nt], af[mt], bb[nt]);
        }
    };

    load_stage(0, 0);
    CP_COMMIT();
    #pragma unroll 1
    for (int kt = 0; kt < K_DIM / BK; kt++) {
        if (kt + 1 < K_DIM / BK) {
            load_stage(kt + 1, (kt + 1) & 1);
            CP_COMMIT();
            CP_WAIT1();
        } else {
            CP_WAIT0();
        }
        __syncthreads();
        compute(kt & 1);
        __syncthreads();
    }

    // epilogue: add bias, store fp32 to g_tmp
    #pragma unroll
    for (int mt = 0; mt < 4; mt++)
        #pragma unroll
        for (int nt = 0; nt < 8; nt++) {
            int row = m0 + wm * 64 + mt * 16 + g;
            int col = n0 + wn * 64 + nt * 8 + 2 * tg;
            float b0 = g_bpack[col], b1 = g_bpack[col + 1];
            float2 v0 = make_float2(acc[mt][nt][0] + b0, acc[mt][nt][1] + b1);
            float2 v1 = make_float2(acc[mt][nt][2] + b0, acc[mt][nt][3] + b1);
            *reinterpret_cast<float2*>(&g_tmp[(size_t)(row    ) * N_DIM + col]) = v0;
            *reinterpret_cast<float2*>(&g_tmp[(size_t)(row + 8) * N_DIM + col]) = v1;
        }
}

// ---------------- kernel 3: gate + weighted feature + final projection ----------
// warp handles 2 tokens; Wg in fp16 smem (half LDS bytes, conflict-free LDS.64).
__global__ __launch_bounds__(256) void gate_kernel(const float* __restrict__ Wg,
                                                   const float* __restrict__ bg,
                                                   const float* __restrict__ Wt,
                                                   const float* __restrict__ bt,
                                                   float* __restrict__ out) {
    __shared__ __half sWg[T_NUM][ETOT][ETOT * H_DIM];   // transposed: [t][j][f], fp16
    __shared__ float sWt[T_NUM][H_DIM];
    __shared__ float sbg[T_NUM][ETOT];
    __shared__ float sbt[T_NUM];

    const int tid = threadIdx.x;
    for (int idx = tid; idx < T_NUM * ETOT * H_DIM * ETOT; idx += 256) {
        int t = idx / (ETOT * H_DIM * ETOT);
        int rem = idx % (ETOT * H_DIM * ETOT);
        int f = rem / ETOT, j = rem % ETOT;
        sWg[t][j][f] = __float2half(Wg[idx]);          // Wg is [t][f][j]
    }
    for (int idx = tid; idx < T_NUM * H_DIM; idx += 256)
        sWt[idx / H_DIM][idx % H_DIM] = Wt[idx];
    if (tid < T_NUM * ETOT) sbg[tid / ETOT][tid % ETOT] = bg[tid];
    if (tid < T_NUM) sbt[tid] = bt[tid];
    __syncthreads();

    const int w = tid >> 5, l = tid & 31;
    const int b0 = blockIdx.x * 16 + w * 2;            // 2 tokens per warp

    // lane l holds h = 4l..4l+3 of every packed expert e, for both tokens
    float4 r[2][NE];
    #pragma unroll
    for (int tok = 0; tok < 2; tok++) {
        const float4* rowp =
            reinterpret_cast<const float4*>(g_tmp + (size_t)(b0 + tok) * N_DIM);
        #pragma unroll
        for (int e = 0; e < NE; e++) r[tok][e] = rowp[e * 32 + l];
    }

    #pragma unroll
    for (int t = 0; t < T_NUM; t++) {
        float lg[2][ETOT];
        #pragma unroll
        for (int tok = 0; tok < 2; tok++)
            #pragma unroll
            for (int j = 0; j < ETOT; j++) lg[tok][j] = 0.f;

        #pragma unroll
        for (int eo = 0; eo < ETOT; eo++) {
            int e = (eo < 2) ? (2 * t + eo) : (eo + 2);
            #pragma unroll
            for (int j = 0; j < ETOT; j++) {
                const __half2* wp =
                    reinterpret_cast<const __half2*>(&sWg[t][j][eo * H_DIM + 4 * l]);
                float2 f01 = __half22float2(wp[0]);
                float2 f23 = __half22float2(wp[1]);
                #pragma unroll
                for (int tok = 0; tok < 2; tok++) {
                    float4 gi = r[tok][e];
                    lg[tok][j] += gi.x * f01.x + gi.y * f01.y +
                                  gi.z * f23.x + gi.w * f23.y;
                }
            }
        }
        #pragma unroll
        for (int tok = 0; tok < 2; tok++) {
            #pragma unroll
            for (int j = 0; j < ETOT; j++) {
                #pragma unroll
                for (int off = 16; off > 0; off >>= 1)
                    lg[tok][j] += __shfl_xor_sync(0xffffffffu, lg[tok][j], off);
                lg[tok][j] += sbg[t][j];
            }
            float m = lg[tok][0];
            #pragma unroll
            for (int j = 1; j < ETOT; j++) m = fmaxf(m, lg[tok][j]);
            float ex[ETOT], ssum = 0.f;
            #pragma unroll
            for (int j = 0; j < ETOT; j++) { ex[j] = expf(lg[tok][j] - m); ssum += ex[j]; }
            float inv = 1.f / ssum;

            float4 feat = make_float4(0.f, 0.f, 0.f, 0.f);
            #pragma unroll
            for (int eo = 0; eo < ETOT; eo++) {
                int e = (eo < 2) ? (2 * t + eo) : (eo + 2);
                float wgt = ex[eo] * inv;
                feat.x += wgt * r[tok][e].x; feat.y += wgt * r[tok][e].y;
                feat.z += wgt * r[tok][e].z; feat.w += wgt * r[tok][e].w;
            }
            float p = feat.x * sWt[t][4 * l] + feat.y * sWt[t][4 * l + 1] +
                      feat.z * sWt[t][4 * l + 2] + feat.w * sWt[t][4 * l + 3];
            #pragma unroll
            for (int off = 16; off > 0; off >>= 1)
                p += __shfl_xor_sync(0xffffffffu, p, off);
            if (l == 0) out[t * B_TOK + b0 + tok] = p + sbt[t];
        }
    }
}

// ---------------- launch ----------------
extern "C" void kernel_launch(void* const* d_in, const int* in_sizes, int n_in,
                              void* d_out, int out_size) {
    const float* x  = (const float*)d_in[0];
    const float* Wc = (const float*)d_in[1];
    const float* bc = (const float*)d_in[2];
    const float* Ws = (const float*)d_in[3];
    const float* bs = (const float*)d_in[4];
    const float* Wg = (const float*)d_in[5];
    const float* bg = (const float*)d_in[6];
    const float* Wt = (const float*)d_in[7];
    const float* bt = (const float*)d_in[8];
    float* out = (float*)d_out;

    prep_w_kernel<<<(K_DIM * N_DIM + 255) / 256, 256>>>(Wc, bc, Ws, bs);

    cudaFuncSetAttribute(gemm_kernel, cudaFuncAttributeMaxDynamicSharedMemorySize,
                         SMEM_BYTES);
    gemm_kernel<<<dim3(N_DIM / BN, B_TOK / BM), 128, SMEM_BYTES>>>(x);

    gate_kernel<<<B_TOK / 16, 256>>>(Wg, bg, Wt, bt, out);
}

// round 7
// speedup vs baseline: 2.1822x; 1.0721x over previous
#include <cuda_runtime.h>
#include <cstdint>

// ---------------- problem constants ----------------
#define B_TOK 65536
#define I_DIM 512
#define H_DIM 128
#define T_NUM 2
#define ETOT  6
#define NE    8                 // packed experts: t0e0,t0e1,t1e0,t1e1,c0..c3
#define N_DIM (NE * H_DIM)      // 1024
#define K_DIM I_DIM             // 512
#define NQ    14                // 12 logit weights + 2 Wt-dot weights

// ---------------- scratch (device globals; no allocs allowed) ----------------
__device__ __align__(256) float g_Wpack[K_DIM * N_DIM];           // [k][n], tf32-rounded
__device__ __align__(256) float g_bpack[N_DIM];
__device__ __align__(256) float g_Wg2[NE * H_DIM * NQ];           // [e][h][q]
__device__ __align__(256) float g_part[(size_t)NE * 2 * B_TOK * 16]; // [e][wn][b][16]

// ---------------- helpers ----------------
__device__ __forceinline__ uint32_t f2tf(float x) {
    uint32_t r;
    asm("cvt.rna.tf32.f32 %0, %1;" : "=r"(r) : "f"(x));
    return r;
}
__device__ __forceinline__ void mma8(float* c, const uint32_t* a, const uint32_t* b) {
    asm volatile(
        "mma.sync.aligned.m16n8k8.row.col.f32.tf32.tf32.f32 "
        "{%0,%1,%2,%3}, {%4,%5,%6,%7}, {%8,%9}, {%0,%1,%2,%3};"
        : "+f"(c[0]), "+f"(c[1]), "+f"(c[2]), "+f"(c[3])
        : "r"(a[0]), "r"(a[1]), "r"(a[2]), "r"(a[3]), "r"(b[0]), "r"(b[1]));
}
#define CP_ASYNC16(dst, src) \
    asm volatile("cp.async.cg.shared.global [%0], [%1], 16;\n" :: "r"(dst), "l"(src))
#define CP_COMMIT() asm volatile("cp.async.commit_group;\n")
#define CP_WAIT2()  asm volatile("cp.async.wait_group 2;\n")
#define CP_WAIT0()  asm volatile("cp.async.wait_group 0;\n")

__device__ __forceinline__ uint32_t smem_u32(const void* p) {
    uint32_t a;
    asm("{ .reg .u64 t; cvta.to.shared.u64 t, %1; cvt.u32.u64 %0, t; }"
        : "=r"(a) : "l"(p));
    return a;
}

// ---------------- kernel 1: pack weights + build epilogue gate table ------------
__global__ void prep_w_kernel(const float* __restrict__ Wc, const float* __restrict__ bc,
                              const float* __restrict__ Ws, const float* __restrict__ bs,
                              const float* __restrict__ Wg, const float* __restrict__ Wt) {
    int idx = blockIdx.x * blockDim.x + threadIdx.x;
    if (idx < K_DIM * N_DIM) {
        int k = idx / N_DIM, n = idx % N_DIM;
        int e = n / H_DIM,   h = n % H_DIM;
        float v = (e < 4) ? Ws[((size_t)e * I_DIM + k) * H_DIM + h]
                          : Wc[((size_t)(e - 4) * I_DIM + k) * H_DIM + h];
        g_Wpack[idx] = __uint_as_float(f2tf(v));
    }
    if (idx < N_DIM) {
        int e = idx / H_DIM, h = idx % H_DIM;
        g_bpack[idx] = (e < 4) ? bs[e * H_DIM + h] : bc[(e - 4) * H_DIM + h];
    }
    if (idx < NE * H_DIM * NQ) {
        int e = idx / (H_DIM * NQ);
        int rem = idx % (H_DIM * NQ);
        int h = rem / NQ, q = rem % NQ;
        float v;
        if (q < 12) {
            int t = q / ETOT, j = q % ETOT;
            // expert e's position in task-t gate input, or inactive
            bool active; int f = 0;
            if (e < 4) { active = ((e >> 1) == t); f = e & 1; }
            else       { active = true;            f = e - 2; }
            v = active ? Wg[((size_t)t * (ETOT * H_DIM) + f * H_DIM + h) * ETOT + j] : 0.f;
        } else {
            int t = q - 12;
            v = Wt[t * H_DIM + h];      // Wt is [T][H][1]
        }
        g_Wg2[idx] = v;
    }
}

// ---------------- kernel 2: fused GEMM + gate-partial epilogue ------------------
// For CTA (e = blockIdx.x, mblk = blockIdx.y): rows m0..m0+255, expert e (128 h).
// Computes acc = x @ Wpack_slice, then per-row 14-vector partials vs g_Wg2[e],
// stored to g_part[e][wn][b][16]. No tmp matrix is ever materialized.
#define BM 256
#define BN 128
#define BK 32
#define NSTAGE 3
#define A_PITCH 36
#define B_PITCH 136
#define A_SZ (BM * A_PITCH)   // 9216 floats
#define B_SZ (BK * B_PITCH)   // 4352 floats
#define STG_SZ (A_SZ + B_SZ)  // floats per stage
#define SMEM_BYTES (NSTAGE * STG_SZ * 4)   // 162816 B

__global__ __launch_bounds__(256) void gemm_kernel(const float* __restrict__ x) {
    extern __shared__ float smem[];

    const int tid  = threadIdx.x;
    const int wid  = tid >> 5, lane = tid & 31;
    const int g    = lane >> 2, tg = lane & 3;
    const int wm   = wid >> 1, wn = wid & 1;        // 4x2 warp grid, 64x64 per warp
    const int e    = blockIdx.x;
    const int m0   = blockIdx.y * BM;
    const int n0   = e * BN;

    float acc[4][8][4];
    #pragma unroll
    for (int i = 0; i < 4; i++)
        #pragma unroll
        for (int j = 0; j < 8; j++)
            #pragma unroll
            for (int c = 0; c < 4; c++) acc[i][j][c] = 0.f;

    auto load_stage = [&](int kt, int buf) {
        const int kb = kt * BK;
        float* As = smem + buf * STG_SZ;
        float* Bs = As + A_SZ;
        const uint32_t sA = smem_u32(As), sB = smem_u32(Bs);
        #pragma unroll
        for (int i = 0; i < 8; i++) {          // A: 256 rows x 8 float4
            int f   = tid + i * 256;
            int row = f >> 3, kc = f & 7;
            const float* src = x + (size_t)(m0 + row) * K_DIM + kb + kc * 4;
            CP_ASYNC16(sA + (uint32_t)(row * A_PITCH + kc * 4) * 4, src);
        }
        #pragma unroll
        for (int i = 0; i < 4; i++) {          // B: 32 rows x 32 float4
            int f = tid + i * 256;
            int k = f >> 5, nc = f & 31;
            const float* src = g_Wpack + (size_t)(kb + k) * N_DIM + n0 + nc * 4;
            CP_ASYNC16(sB + (uint32_t)(k * B_PITCH + nc * 4) * 4, src);
        }
        CP_COMMIT();
    };

    auto compute = [&](int buf) {
        const float*    A  = smem + buf * STG_SZ;
        const uint32_t* Bt = reinterpret_cast<const uint32_t*>(A + A_SZ);
        #pragma unroll
        for (int ks = 0; ks < 4; ks++) {
            const int kb = ks * 8;
            uint32_t af[4][4];
            #pragma unroll
            for (int mt = 0; mt < 4; mt++) {
                int r0 = wm * 64 + mt * 16 + g;
                af[mt][0] = f2tf(A[(r0    ) * A_PITCH + kb + tg    ]);
                af[mt][1] = f2tf(A[(r0 + 8) * A_PITCH + kb + tg    ]);
                af[mt][2] = f2tf(A[(r0    ) * A_PITCH + kb + tg + 4]);
                af[mt][3] = f2tf(A[(r0 + 8) * A_PITCH + kb + tg + 4]);
            }
            uint32_t bb[8][2];
            #pragma unroll
            for (int nt = 0; nt < 8; nt++) {
                int c0 = wn * 64 + nt * 8 + g;
                bb[nt][0] = Bt[(kb + tg    ) * B_PITCH + c0];
                bb[nt][1] = Bt[(kb + tg + 4) * B_PITCH + c0];
            }
            #pragma unroll
            for (int mt = 0; mt < 4; mt++)
                #pragma unroll
                for (int nt = 0; nt < 8; nt++)
                    mma8(acc[mt][nt], af[mt], bb[nt]);
        }
    };

    load_stage(0, 0);
    load_stage(1, 1);
    #pragma unroll 1
    for (int kt = 0; kt < K_DIM / BK; kt++) {
        if (kt + 2 < K_DIM / BK) {
            load_stage(kt + 2, (kt + 2) % NSTAGE);
            CP_WAIT2();
        } else {
            CP_WAIT0();
        }
        __syncthreads();
        compute(kt % NSTAGE);
        __syncthreads();
    }

    // ---------------- epilogue: gate partials (reuse stage smem) ----------------
    float* sWg = smem;                               // 128*NQ floats = 7168 B
    for (int i = tid; i < H_DIM * NQ; i += 256)
        sWg[i] = g_Wg2[(size_t)e * H_DIM * NQ + i];
    __syncthreads();

    // bias for this thread's 16 cols
    float bias[8][2];
    #pragma unroll
    for (int nt = 0; nt < 8; nt++) {
        int col = n0 + wn * 64 + nt * 8 + 2 * tg;
        bias[nt][0] = g_bpack[col];
        bias[nt][1] = g_bpack[col + 1];
    }

    #pragma unroll
    for (int half = 0; half < 2; half++) {           // mt pairs -> 4 rows per pass
        float part[4][NQ];
        #pragma unroll
        for (int r = 0; r < 4; r++)
            #pragma unroll
            for (int q = 0; q < NQ; q++) part[r][q] = 0.f;

        #pragma unroll
        for (int nt = 0; nt < 8; nt++)
            #pragma unroll
            for (int h2 = 0; h2 < 2; h2++) {
                int hh = wn * 64 + nt * 8 + 2 * tg + h2;
                float w[NQ];
                #pragma unroll
                for (int q = 0; q < NQ; q++) w[q] = sWg[hh * NQ + q];
                #pragma unroll
                for (int mt2 = 0; mt2 < 2; mt2++)
                    #pragma unroll
                    for (int rr = 0; rr < 2; rr++) {
                        float v = acc[half * 2 + mt2][nt][rr * 2 + h2] + bias[nt][h2];
                        #pragma unroll
                        for (int q = 0; q < NQ; q++) part[mt2 * 2 + rr][q] += v * w[q];
                    }
            }

        // reduce over tg quad, then lane tg==0 stores
        #pragma unroll
        for (int r = 0; r < 4; r++) {
            #pragma unroll
            for (int q = 0; q < NQ; q++) {
                part[r][q] += __shfl_xor_sync(0xffffffffu, part[r][q], 1);
                part[r][q] += __shfl_xor_sync(0xffffffffu, part[r][q], 2);
            }
            if (tg == 0) {
                int mt = half * 2 + (r >> 1);
                int row = m0 + wm * 64 + mt * 16 + g + (r & 1) * 8;
                float* dst = g_part + (((size_t)(e * 2 + wn) * B_TOK + row) << 4);
                float4 v0 = make_float4(part[r][0], part[r][1], part[r][2],  part[r][3]);
                float4 v1 = make_float4(part[r][4], part[r][5], part[r][6],  part[r][7]);
                float4 v2 = make_float4(part[r][8], part[r][9], part[r][10], part[r][11]);
                float4 v3 = make_float4(part[r][12], part[r][13], 0.f, 0.f);
                reinterpret_cast<float4*>(dst)[0] = v0;
                reinterpret_cast<float4*>(dst)[1] = v1;
                reinterpret_cast<float4*>(dst)[2] = v2;
                reinterpret_cast<float4*>(dst)[3] = v3;
            }
        }
    }
}

// ---------------- kernel 3: combine partials, softmax, output -------------------
__global__ __launch_bounds__(256) void gate_kernel(const float* __restrict__ bg,
                                                   const float* __restrict__ bt,
                                                   float* __restrict__ out) {
    const int b = blockIdx.x * 256 + threadIdx.x;

    float lg[12];
    #pragma unroll
    for (int q = 0; q < 12; q++) lg[q] = 0.f;
    float dots[NE][2];
    #pragma unroll
    for (int e = 0; e < NE; e++) { dots[e][0] = 0.f; dots[e][1] = 0.f; }

    #pragma unroll
    for (int s = 0; s < 16; s++) {
        const float4* p =
            reinterpret_cast<const float4*>(g_part + (((size_t)s * B_TOK + b) << 4));
        float4 v0 = p[0], v1 = p[1], v2 = p[2], v3 = p[3];
        lg[0] += v0.x; lg[1] += v0.y; lg[2]  += v0.z; lg[3]  += v0.w;
        lg[4] += v1.x; lg[5] += v1.y; lg[6]  += v1.z; lg[7]  += v1.w;
        lg[8] += v2.x; lg[9] += v2.y; lg[10] += v2.z; lg[11] += v2.w;
        int e = s >> 1;
        dots[e][0] += v3.x; dots[e][1] += v3.y;
    }

    #pragma unroll
    for (int t = 0; t < T_NUM; t++) {
        float l[ETOT];
        #pragma unroll
        for (int j = 0; j < ETOT; j++) l[j] = lg[t * ETOT + j] + bg[t * ETOT + j];
        float m = l[0];
        #pragma unroll
        for (int j = 1; j < ETOT; j++) m = fmaxf(m, l[j]);
        float ex[ETOT], ssum = 0.f;
        #pragma unroll
        for (int j = 0; j < ETOT; j++) { ex[j] = expf(l[j] - m); ssum += ex[j]; }
        float inv = 1.f / ssum;
        float o = 0.f;
        #pragma unroll
        for (int eo = 0; eo < ETOT; eo++) {
            int e = (eo < 2) ? (2 * t + eo) : (eo + 2);
            o += ex[eo] * inv * dots[e][t];
        }
        out[t * B_TOK + b] = o + bt[t];
    }
}

// ---------------- launch ----------------
extern "C" void kernel_launch(void* const* d_in, const int* in_sizes, int n_in,
                              void* d_out, int out_size) {
    const float* x  = (const float*)d_in[0];
    const float* Wc = (const float*)d_in[1];
    const float* bc = (const float*)d_in[2];
    const float* Ws = (const float*)d_in[3];
    const float* bs = (const float*)d_in[4];
    const float* Wg = (const float*)d_in[5];
    const float* bg = (const float*)d_in[6];
    const float* Wt = (const float*)d_in[7];
    const float* bt = (const float*)d_in[8];
    float* out = (float*)d_out;

    prep_w_kernel<<<(K_DIM * N_DIM + 255) / 256, 256>>>(Wc, bc, Ws, bs, Wg, Wt);

    cudaFuncSetAttribute(gemm_kernel, cudaFuncAttributeMaxDynamicSharedMemorySize,
                         SMEM_BYTES);
    gemm_kernel<<<dim3(NE, B_TOK / BM), 256, SMEM_BYTES>>>(x);

    gate_kernel<<<B_TOK / 256, 256>>>(bg, bt, out);
}

// round 8
// speedup vs baseline: 3.3081x; 1.5160x over previous
#include <cuda_runtime.h>
#include <cuda_fp16.h>
#include <cstdint>

// ---------------- problem constants ----------------
#define B_TOK 65536
#define I_DIM 512
#define H_DIM 128
#define T_NUM 2
#define ETOT  6
#define NE    8                 // packed experts: t0e0,t0e1,t1e0,t1e1,c0..c3
#define N_DIM (NE * H_DIM)      // 1024
#define K_DIM I_DIM             // 512
#define NQ    14                // 12 logit weights + 2 Wt-dot weights

// ---------------- scratch (device globals; no allocs allowed) ----------------
__device__ __align__(256) __half g_xh[(size_t)B_TOK * K_DIM];     // fp16 x (64 MB)
__device__ __align__(256) __half g_Wh[N_DIM * K_DIM];             // [n][k] fp16 (1 MB)
__device__ __align__(256) float  g_bpack[N_DIM];
__device__ __align__(256) float  g_Wg2[NE * H_DIM * NQ];          // [e][h][q]
__device__ __align__(256) float  g_part[(size_t)NE * 2 * B_TOK * 16]; // [e][wn][b][16]

// ---------------- helpers ----------------
__device__ __forceinline__ void mma16(float* c, const uint32_t* a, const uint32_t* b) {
    asm volatile(
        "mma.sync.aligned.m16n8k16.row.col.f32.f16.f16.f32 "
        "{%0,%1,%2,%3}, {%4,%5,%6,%7}, {%8,%9}, {%0,%1,%2,%3};"
        : "+f"(c[0]), "+f"(c[1]), "+f"(c[2]), "+f"(c[3])
        : "r"(a[0]), "r"(a[1]), "r"(a[2]), "r"(a[3]), "r"(b[0]), "r"(b[1]));
}
#define CP_ASYNC16(dst, src) \
    asm volatile("cp.async.cg.shared.global [%0], [%1], 16;\n" :: "r"(dst), "l"(src))
#define CP_COMMIT() asm volatile("cp.async.commit_group;\n")
#define CP_WAIT2()  asm volatile("cp.async.wait_group 2;\n")
#define CP_WAIT1()  asm volatile("cp.async.wait_group 1;\n")
#define CP_WAIT0()  asm volatile("cp.async.wait_group 0;\n")

__device__ __forceinline__ uint32_t smem_u32(const void* p) {
    uint32_t a;
    asm("{ .reg .u64 t; cvta.to.shared.u64 t, %1; cvt.u32.u64 %0, t; }"
        : "=r"(a) : "l"(p));
    return a;
}

// ---------------- kernel 1: convert x, pack W, build gate table ----------------
__global__ void prep_kernel(const float* __restrict__ x,
                            const float* __restrict__ Wc, const float* __restrict__ bc,
                            const float* __restrict__ Ws, const float* __restrict__ bs,
                            const float* __restrict__ Wg, const float* __restrict__ Wt) {
    const int idx = blockIdx.x * blockDim.x + threadIdx.x;   // 0 .. 8388607

    // x -> fp16 (4 elements per thread)
    {
        float4 v = reinterpret_cast<const float4*>(x)[idx];
        __half2 h0 = __floats2half2_rn(v.x, v.y);
        __half2 h1 = __floats2half2_rn(v.z, v.w);
        uint2 pk = make_uint2(*reinterpret_cast<uint32_t*>(&h0),
                              *reinterpret_cast<uint32_t*>(&h1));
        reinterpret_cast<uint2*>(g_xh)[idx] = pk;
    }
    // W pack: [n][k] fp16
    if (idx < N_DIM * K_DIM) {
        int n = idx / K_DIM, k = idx % K_DIM;
        int e = n / H_DIM,   h = n % H_DIM;
        float v = (e < 4) ? Ws[((size_t)e * I_DIM + k) * H_DIM + h]
                          : Wc[((size_t)(e - 4) * I_DIM + k) * H_DIM + h];
        g_Wh[idx] = __float2half(v);
    }
    if (idx < N_DIM) {
        int e = idx / H_DIM, h = idx % H_DIM;
        g_bpack[idx] = (e < 4) ? bs[e * H_DIM + h] : bc[(e - 4) * H_DIM + h];
    }
    if (idx < NE * H_DIM * NQ) {
        int e = idx / (H_DIM * NQ);
        int rem = idx % (H_DIM * NQ);
        int h = rem / NQ, q = rem % NQ;
        float v;
        if (q < 12) {
            int t = q / ETOT, j = q % ETOT;
            bool active; int f = 0;
            if (e < 4) { active = ((e >> 1) == t); f = e & 1; }
            else       { active = true;            f = e - 2; }
            v = active ? Wg[((size_t)t * (ETOT * H_DIM) + f * H_DIM + h) * ETOT + j] : 0.f;
        } else {
            v = Wt[(q - 12) * H_DIM + h];
        }
        g_Wg2[idx] = v;
    }
}

// ---------------- kernel 2: fp16 GEMM (m16n8k16) + gate-partial epilogue --------
#define BM 256
#define BN 128
#define BKH 64                 // K halves per chunk (128 B rows)
#define NCHUNK (K_DIM / BKH)   // 8
#define NSTAGE 3
#define A_PITCH 72             // halves; bank = 4g+tg -> conflict-free; 144B % 16 == 0
#define A_SZ (BM * A_PITCH)    // 18432 halves
#define B_SZ (BN * A_PITCH)    // 9216 halves
#define STG_H (A_SZ + B_SZ)    // halves per stage
#define SMEM_BYTES (NSTAGE * STG_H * 2)   // 165888 B

__global__ __launch_bounds__(256) void gemm_kernel() {
    extern __shared__ __half smem[];

    const int tid  = threadIdx.x;
    const int wid  = tid >> 5, lane = tid & 31;
    const int g    = lane >> 2, tg = lane & 3;
    const int wm   = wid >> 1, wn = wid & 1;        // 4x2 warp grid, 64x64 per warp
    const int e    = blockIdx.x;
    const int m0   = blockIdx.y * BM;
    const int n0   = e * BN;

    float acc[4][8][4];
    #pragma unroll
    for (int i = 0; i < 4; i++)
        #pragma unroll
        for (int j = 0; j < 8; j++)
            #pragma unroll
            for (int c = 0; c < 4; c++) acc[i][j][c] = 0.f;

    auto load_stage = [&](int kt, int buf) {
        const int kb = kt * BKH;                     // in halves
        __half* As = smem + buf * STG_H;
        __half* Bs = As + A_SZ;
        const uint32_t sA = smem_u32(As), sB = smem_u32(Bs);
        #pragma unroll
        for (int i = 0; i < 8; i++) {                // A: 256 rows x 8 chunks(16B)
            int f   = tid + i * 256;
            int row = f >> 3, kc = f & 7;            // kc: 16B chunk = 8 halves
            const __half* src = g_xh + (size_t)(m0 + row) * K_DIM + kb + kc * 8;
            CP_ASYNC16(sA + (uint32_t)(row * A_PITCH + kc * 8) * 2, src);
        }
        #pragma unroll
        for (int i = 0; i < 4; i++) {                // B: 128 rows x 8 chunks(16B)
            int f   = tid + i * 256;
            int row = f >> 3, kc = f & 7;
            const __half* src = g_Wh + (size_t)(n0 + row) * K_DIM + kb + kc * 8;
            CP_ASYNC16(sB + (uint32_t)(row * A_PITCH + kc * 8) * 2, src);
        }
        CP_COMMIT();
    };

    auto compute = [&](int buf) {
        const __half* As = smem + buf * STG_H;
        const __half* Bs = As + A_SZ;
        const uint32_t* A32 = reinterpret_cast<const uint32_t*>(As);
        const uint32_t* B32 = reinterpret_cast<const uint32_t*>(Bs);
        #pragma unroll
        for (int ks = 0; ks < 4; ks++) {             // 4 x k16 per chunk
            const int kb = ks * 8;                   // half2 units: 16 halves = 8 h2
            uint32_t af[4][4];
            #pragma unroll
            for (int mt = 0; mt < 4; mt++) {
                int r0 = wm * 64 + mt * 16 + g;
                const uint32_t* a0 = A32 + (r0    ) * (A_PITCH / 2) + kb;
                const uint32_t* a1 = A32 + (r0 + 8) * (A_PITCH / 2) + kb;
                af[mt][0] = a0[tg];
                af[mt][1] = a1[tg];
                af[mt][2] = a0[tg + 4];
                af[mt][3] = a1[tg + 4];
            }
            uint32_t bb[8][2];
            #pragma unroll
            for (int nt = 0; nt < 8; nt++) {
                int c0 = wn * 64 + nt * 8 + g;
                const uint32_t* bp = B32 + c0 * (A_PITCH / 2) + kb;
                bb[nt][0] = bp[tg];
                bb[nt][1] = bp[tg + 4];
            }
            #pragma unroll
            for (int mt = 0; mt < 4; mt++)
                #pragma unroll
                for (int nt = 0; nt < 8; nt++)
                    mma16(acc[mt][nt], af[mt], bb[nt]);
        }
    };

    load_stage(0, 0);
    load_stage(1, 1);
    #pragma unroll 1
    for (int kt = 0; kt < NCHUNK; kt++) {
        if (kt + 2 < NCHUNK) {
            load_stage(kt + 2, (kt + 2) % NSTAGE);
            CP_WAIT2();
        } else if (kt + 2 == NCHUNK) {
            CP_WAIT1();
        } else {
            CP_WAIT0();
        }
        __syncthreads();
        compute(kt % NSTAGE);
        __syncthreads();
    }

    // ---------------- epilogue: gate partials (reuse stage smem) ----------------
    float* sWg = reinterpret_cast<float*>(smem);     // 128*NQ floats
    for (int i = tid; i < H_DIM * NQ; i += 256)
        sWg[i] = g_Wg2[(size_t)e * H_DIM * NQ + i];
    __syncthreads();

    float bias[8][2];
    #pragma unroll
    for (int nt = 0; nt < 8; nt++) {
        int col = n0 + wn * 64 + nt * 8 + 2 * tg;
        bias[nt][0] = g_bpack[col];
        bias[nt][1] = g_bpack[col + 1];
    }

    #pragma unroll
    for (int half = 0; half < 2; half++) {
        float part[4][NQ];
        #pragma unroll
        for (int r = 0; r < 4; r++)
            #pragma unroll
            for (int q = 0; q < NQ; q++) part[r][q] = 0.f;

        #pragma unroll
        for (int nt = 0; nt < 8; nt++)
            #pragma unroll
            for (int h2 = 0; h2 < 2; h2++) {
                int hh = wn * 64 + nt * 8 + 2 * tg + h2;
                float w[NQ];
                #pragma unroll
                for (int q = 0; q < NQ; q++) w[q] = sWg[hh * NQ + q];
                #pragma unroll
                for (int mt2 = 0; mt2 < 2; mt2++)
                    #pragma unroll
                    for (int rr = 0; rr < 2; rr++) {
                        float v = acc[half * 2 + mt2][nt][rr * 2 + h2] + bias[nt][h2];
                        #pragma unroll
                        for (int q = 0; q < NQ; q++) part[mt2 * 2 + rr][q] += v * w[q];
                    }
            }

        #pragma unroll
        for (int r = 0; r < 4; r++) {
            #pragma unroll
            for (int q = 0; q < NQ; q++) {
                part[r][q] += __shfl_xor_sync(0xffffffffu, part[r][q], 1);
                part[r][q] += __shfl_xor_sync(0xffffffffu, part[r][q], 2);
            }
            if (tg == 0) {
                int mt = half * 2 + (r >> 1);
                int row = m0 + wm * 64 + mt * 16 + g + (r & 1) * 8;
                float* dst = g_part + (((size_t)(e * 2 + wn) * B_TOK + row) << 4);
                reinterpret_cast<float4*>(dst)[0] =
                    make_float4(part[r][0], part[r][1], part[r][2],  part[r][3]);
                reinterpret_cast<float4*>(dst)[1] =
                    make_float4(part[r][4], part[r][5], part[r][6],  part[r][7]);
                reinterpret_cast<float4*>(dst)[2] =
                    make_float4(part[r][8], part[r][9], part[r][10], part[r][11]);
                reinterpret_cast<float4*>(dst)[3] =
                    make_float4(part[r][12], part[r][13], 0.f, 0.f);
            }
        }
    }
}

// ---------------- kernel 3: combine partials, softmax, output -------------------
__global__ __launch_bounds__(256) void gate_kernel(const float* __restrict__ bg,
                                                   const float* __restrict__ bt,
                                                   float* __restrict__ out) {
    const int b = blockIdx.x * 256 + threadIdx.x;

    float lg[12];
    #pragma unroll
    for (int q = 0; q < 12; q++) lg[q] = 0.f;
    float dots[NE][2];
    #pragma unroll
    for (int e = 0; e < NE; e++) { dots[e][0] = 0.f; dots[e][1] = 0.f; }

    #pragma unroll
    for (int s = 0; s < 16; s++) {
        const float4* p =
            reinterpret_cast<const float4*>(g_part + (((size_t)s * B_TOK + b) << 4));
        float4 v0 = p[0], v1 = p[1], v2 = p[2], v3 = p[3];
        lg[0] += v0.x; lg[1] += v0.y; lg[2]  += v0.z; lg[3]  += v0.w;
        lg[4] += v1.x; lg[5] += v1.y; lg[6]  += v1.z; lg[7]  += v1.w;
        lg[8] += v2.x; lg[9] += v2.y; lg[10] += v2.z; lg[11] += v2.w;
        int e = s >> 1;
        dots[e][0] += v3.x; dots[e][1] += v3.y;
    }

    #pragma unroll
    for (int t = 0; t < T_NUM; t++) {
        float l[ETOT];
        #pragma unroll
        for (int j = 0; j < ETOT; j++) l[j] = lg[t * ETOT + j] + bg[t * ETOT + j];
        float m = l[0];
        #pragma unroll
        for (int j = 1; j < ETOT; j++) m = fmaxf(m, l[j]);
        float ex[ETOT], ssum = 0.f;
        #pragma unroll
        for (int j = 0; j < ETOT; j++) { ex[j] = expf(l[j] - m); ssum += ex[j]; }
        float inv = 1.f / ssum;
        float o = 0.f;
        #pragma unroll
        for (int eo = 0; eo < ETOT; eo++) {
            int e = (eo < 2) ? (2 * t + eo) : (eo + 2);
            o += ex[eo] * inv * dots[e][t];
        }
        out[t * B_TOK + b] = o + bt[t];
    }
}

// ---------------- dummy: pads launch sequence so ncu -s 5 lands on gemm ---------
__global__ void dummy_kernel() {}

// ---------------- launch ----------------
extern "C" void kernel_launch(void* const* d_in, const int* in_sizes, int n_in,
                              void* d_out, int out_size) {
    const float* x  = (const float*)d_in[0];
    const float* Wc = (const float*)d_in[1];
    const float* bc = (const float*)d_in[2];
    const float* Ws = (const float*)d_in[3];
    const float* bs = (const float*)d_in[4];
    const float* Wg = (const float*)d_in[5];
    const float* bg = (const float*)d_in[6];
    const float* Wt = (const float*)d_in[7];
    const float* bt = (const float*)d_in[8];
    float* out = (float*)d_out;

    prep_kernel<<<(B_TOK * K_DIM / 4) / 256, 256>>>(x, Wc, bc, Ws, bs, Wg, Wt);

    cudaFuncSetAttribute(gemm_kernel, cudaFuncAttributeMaxDynamicSharedMemorySize,
                         SMEM_BYTES);
    gemm_kernel<<<dim3(NE, B_TOK / BM), 256, SMEM_BYTES>>>();

    gate_kernel<<<B_TOK / 256, 256>>>(bg, bt, out);
    dummy_kernel<<<1, 1>>>();
}